// round 6
// baseline (speedup 1.0000x reference)
#include <cuda_runtime.h>

// out[b,t,c] = (1/(t+1)) * sum_{s<=t} x[b,s,c]
// Causal running mean along T. Three-kernel chunked scan:
//   pass1: per-chunk sums          (512 blocks, streams x into L2)
//   mid:   exclusive scan of chunk sums in place (tiny, L2-resident)
//   pass2: offset + local scan     (512 blocks, one offset load, no lookback)

#define BB 4
#define TT 4096
#define CC 1024
#define C4 (CC / 4)             // 256 float4 columns
#define NCHUNK 128
#define CHUNK_T (TT / NCHUNK)   // 32
#define NTHREADS 256

// Scratch: per-(b,chunk) chunk sums over all C. 4*128*1024*4B = 2 MB.
// After mid_scan, holds the EXCLUSIVE prefix across chunks.
__device__ float4 g_partials[BB * NCHUNK * C4];

__global__ void __launch_bounds__(NTHREADS)
pass1_chunk_sums(const float* __restrict__ x) {
    const int c4    = threadIdx.x;
    const int chunk = blockIdx.y;
    const int b     = blockIdx.z;

    const float4* p = (const float4*)(x + ((size_t)b * TT + (size_t)chunk * CHUNK_T) * CC) + c4;

    float4 a0 = make_float4(0.f, 0.f, 0.f, 0.f);
    float4 a1 = make_float4(0.f, 0.f, 0.f, 0.f);
#pragma unroll 8
    for (int t = 0; t < CHUNK_T; t += 2) {
        float4 v0 = p[(size_t)t * C4];
        float4 v1 = p[(size_t)(t + 1) * C4];
        a0.x += v0.x; a0.y += v0.y; a0.z += v0.z; a0.w += v0.w;
        a1.x += v1.x; a1.y += v1.y; a1.z += v1.z; a1.w += v1.w;
    }
    float4 s;
    s.x = a0.x + a1.x; s.y = a0.y + a1.y; s.z = a0.z + a1.z; s.w = a0.w + a1.w;
    g_partials[(b * NCHUNK + chunk) * C4 + c4] = s;
}

// One thread per (b, c4) column: turn chunk sums into exclusive prefixes, in place.
// grid = (4 c4-groups, 1, 4 b), block = 64 threads -> 1024 threads total.
__global__ void __launch_bounds__(64)
mid_scan() {
    const int c4 = blockIdx.x * 64 + threadIdx.x;
    const int b  = blockIdx.z;

    float4* part = &g_partials[b * NCHUNK * C4 + c4];
    float4 acc = make_float4(0.f, 0.f, 0.f, 0.f);
#pragma unroll 8
    for (int k = 0; k < NCHUNK; ++k) {
        float4 v = part[(size_t)k * C4];
        part[(size_t)k * C4] = acc;             // exclusive prefix
        acc.x += v.x; acc.y += v.y; acc.z += v.z; acc.w += v.w;
    }
}

__global__ void __launch_bounds__(NTHREADS)
pass2_scan(const float* __restrict__ x, float* __restrict__ out) {
    const int c4    = threadIdx.x;
    const int chunk = blockIdx.y;
    const int b     = blockIdx.z;

    // Single precomputed exclusive-prefix offset.
    float4 acc = g_partials[(b * NCHUNK + chunk) * C4 + c4];

    const size_t base = ((size_t)b * TT + (size_t)chunk * CHUNK_T) * CC;
    const float4* p = (const float4*)(x + base) + c4;
    float4*       q = (float4*)(out + base) + c4;

    const int t0 = chunk * CHUNK_T;
#pragma unroll 8
    for (int t = 0; t < CHUNK_T; ++t) {
        float4 v = __ldcs(&p[(size_t)t * C4]);   // last use of x: stream it
        acc.x += v.x; acc.y += v.y; acc.z += v.z; acc.w += v.w;
        float inv = __fdividef(1.0f, (float)(t0 + t + 1));
        float4 o;
        o.x = acc.x * inv; o.y = acc.y * inv; o.z = acc.z * inv; o.w = acc.w * inv;
        __stcs(&q[(size_t)t * C4], o);           // evict-first write stream
    }
}

extern "C" void kernel_launch(void* const* d_in, const int* in_sizes, int n_in,
                              void* d_out, int out_size) {
    const float* x = (const float*)d_in[0];
    float* out = (float*)d_out;

    dim3 grid(1, NCHUNK, BB);   // 512 blocks
    dim3 block(NTHREADS);

    pass1_chunk_sums<<<grid, block>>>(x);
    mid_scan<<<dim3(C4 / 64, 1, BB), 64>>>();
    pass2_scan<<<grid, block>>>(x, out);
}

// round 9
// speedup vs baseline: 1.2629x; 1.2629x over previous
#include <cuda_runtime.h>

// out[b,t,c] = (1/(t+1)) * sum_{s<=t} x[b,s,c]
// Causal running mean along T. Three-kernel chunked scan with front-batched
// loads (MLP=8 per thread) to cover DRAM latency.

#define BB 4
#define TT 4096
#define CC 1024
#define C4 (CC / 4)             // 256 float4 columns
#define NCHUNK 128
#define CHUNK_T (TT / NCHUNK)   // 32
#define NTHREADS 256
#define BATCH 8

// Scratch: per-(b,chunk) chunk sums over all C. 2 MB.
// After mid_scan, holds the EXCLUSIVE prefix across chunks.
__device__ float4 g_partials[BB * NCHUNK * C4];

__global__ void __launch_bounds__(NTHREADS, 3)
pass1_chunk_sums(const float* __restrict__ x) {
    const int c4    = threadIdx.x;
    const int chunk = blockIdx.y;
    const int b     = blockIdx.z;

    const float4* __restrict__ p =
        (const float4*)(x + ((size_t)b * TT + (size_t)chunk * CHUNK_T) * CC) + c4;

    float4 a0 = make_float4(0.f, 0.f, 0.f, 0.f);
    float4 a1 = make_float4(0.f, 0.f, 0.f, 0.f);
#pragma unroll
    for (int batch = 0; batch < CHUNK_T / BATCH; ++batch) {
        float4 buf[BATCH];
#pragma unroll
        for (int i = 0; i < BATCH; ++i)
            buf[i] = p[(size_t)(batch * BATCH + i) * C4];
#pragma unroll
        for (int i = 0; i < BATCH; i += 2) {
            a0.x += buf[i].x;   a0.y += buf[i].y;   a0.z += buf[i].z;   a0.w += buf[i].w;
            a1.x += buf[i+1].x; a1.y += buf[i+1].y; a1.z += buf[i+1].z; a1.w += buf[i+1].w;
        }
    }
    float4 s;
    s.x = a0.x + a1.x; s.y = a0.y + a1.y; s.z = a0.z + a1.z; s.w = a0.w + a1.w;
    g_partials[(b * NCHUNK + chunk) * C4 + c4] = s;
}

// One thread per (b, c4) column: chunk sums -> exclusive prefixes, in place.
// Data is L2-resident (pass1 just wrote it). 8-deep prefetch batches.
__global__ void __launch_bounds__(64)
mid_scan() {
    const int c4 = blockIdx.x * 64 + threadIdx.x;
    const int b  = blockIdx.z;

    float4* __restrict__ part = &g_partials[b * NCHUNK * C4 + c4];
    float4 acc = make_float4(0.f, 0.f, 0.f, 0.f);
#pragma unroll
    for (int kb = 0; kb < NCHUNK / 8; ++kb) {
        float4 buf[8];
#pragma unroll
        for (int i = 0; i < 8; ++i)
            buf[i] = part[(size_t)(kb * 8 + i) * C4];
#pragma unroll
        for (int i = 0; i < 8; ++i) {
            part[(size_t)(kb * 8 + i) * C4] = acc;   // exclusive prefix
            acc.x += buf[i].x; acc.y += buf[i].y; acc.z += buf[i].z; acc.w += buf[i].w;
        }
    }
}

__global__ void __launch_bounds__(NTHREADS, 3)
pass2_scan(const float* __restrict__ x, float* __restrict__ out) {
    const int c4    = threadIdx.x;
    const int chunk = blockIdx.y;
    const int b     = blockIdx.z;

    float4 acc = g_partials[(b * NCHUNK + chunk) * C4 + c4];

    const size_t base = ((size_t)b * TT + (size_t)chunk * CHUNK_T) * CC;
    const float4* __restrict__ p = (const float4*)(x + base) + c4;
    float4*       __restrict__ q = (float4*)(out + base) + c4;

    const int t0 = chunk * CHUNK_T;
#pragma unroll
    for (int batch = 0; batch < CHUNK_T / BATCH; ++batch) {
        float4 buf[BATCH];
#pragma unroll
        for (int i = 0; i < BATCH; ++i)
            buf[i] = __ldcg(&p[(size_t)(batch * BATCH + i) * C4]);   // L2 hit expected
#pragma unroll
        for (int i = 0; i < BATCH; ++i) {
            const int t = batch * BATCH + i;
            acc.x += buf[i].x; acc.y += buf[i].y; acc.z += buf[i].z; acc.w += buf[i].w;
            float inv = __fdividef(1.0f, (float)(t0 + t + 1));
            float4 o;
            o.x = acc.x * inv; o.y = acc.y * inv; o.z = acc.z * inv; o.w = acc.w * inv;
            __stcs(&q[(size_t)t * C4], o);   // evict-first write stream
        }
    }
}

extern "C" void kernel_launch(void* const* d_in, const int* in_sizes, int n_in,
                              void* d_out, int out_size) {
    const float* x = (const float*)d_in[0];
    float* out = (float*)d_out;

    dim3 grid(1, NCHUNK, BB);   // 512 blocks
    dim3 block(NTHREADS);

    pass1_chunk_sums<<<grid, block>>>(x);
    mid_scan<<<dim3(C4 / 64, 1, BB), 64>>>();
    pass2_scan<<<grid, block>>>(x, out);
}